// round 12
// baseline (speedup 1.0000x reference)
#include <cuda_runtime.h>
#include <cstdint>

#define NB   32
#define H    1024
#define W    1024
#define BH   73
#define BW   73
#define BS   14                  // block stride = 16 - 3 + 1
#define NROWS (NB*BH)            // 2336 flag rows
#define TOTAL (NB*BH*BW)         // 170528

__device__ unsigned long long g_acc;     // low32: running count, high32: done ctr
__device__ unsigned g_bits[NROWS * 3];   // 73-bit mask per row (slow path only)
__device__ int g_csum[NROWS];
__device__ int g_coff[NROWS];            // fixup scratch

// ---------------------------------------------------------------------------
// Rare-path fixup (p ~ 2^-244): some window was inactive, so the speculative
// layout (prefix = 73*row) is wrong. Rebuild the whole output from
// g_csum/g_bits with this single CTA. Perf-irrelevant; correctness only.
// ---------------------------------------------------------------------------
__device__ __noinline__ void fixup(float* __restrict__ out, int total) {
    const int t = threadIdx.x;
    const int nthr = blockDim.x;
    if (t == 0) {
        int acc = 0;
        for (int i = 0; i < NROWS; i++) { g_coff[i] = acc; acc += g_csum[i]; }
    }
    __syncthreads();
    for (int g = t; g < TOTAL; g += nthr) {
        int row = g / BW, col = g - (g / BW) * BW;
        int cnt = g_csum[row], off = g_coff[row];
        int below, f;
        if (cnt == BW) { below = col; f = 1; }
        else {
            unsigned w0 = g_bits[row * 3 + 0];
            unsigned w1 = g_bits[row * 3 + 1];
            unsigned w2 = g_bits[row * 3 + 2];
            unsigned lm = (1u << (col & 31)) - 1u;
            if (col < 32)      { below = __popc(w0 & lm);                           f = (w0 >> col) & 1; }
            else if (col < 64) { below = __popc(w0) + __popc(w1 & lm);              f = (w1 >> (col - 32)) & 1; }
            else               { below = __popc(w0) + __popc(w1) + __popc(w2 & lm); f = (w2 >> (col - 64)) & 1; }
        }
        if (f) {
            int pos = off + below;
            int i0 = row / BH;
            out[3 * pos + 0] = (float)i0;
            out[3 * pos + 1] = (float)(row - i0 * BH);
            out[3 * pos + 2] = (float)col;
        } else {
            int pos = total + (g - (off + below));
            out[3 * pos + 0] = (float)NB;
            out[3 * pos + 1] = (float)BH;
            out[3 * pos + 2] = (float)BW;
        }
    }
}

// ---------------------------------------------------------------------------
// Single fused kernel: pad + 16x16/stride14 max-pool + threshold + compact.
// 128 threads per CTA, one CTA per (n, by) strip -> 2336 CTAs x 128 thr =
// 299k threads = ONE full wave at 16 CTAs/SM. Each thread issues TWO
// independent float4 loads (chunks t and t+128 of the probe row, same DRAM
// page) -> 2x in-flight bytes per thread vs R11 at identical byte totals.
//  1) Speculative output triples at prefix 73*cta, issued in the load shadow.
//  2) Ballot bitmap of hot 4-chunks; window active if any fully-contained
//     chunk is hot (undecided p = 2^-12 -> ~40 slow strips/launch).
//  3) Slow path: full 16-row colmax with 128 threads x 2 chunks.
//  4) atom.add.release.gpu packs (count, done); last CTA writes the count
//     slot, runs fixup if count != TOTAL (never in practice), resets g_acc.
// ---------------------------------------------------------------------------
__global__ __launch_bounds__(128, 16) void fused_kernel(const float* __restrict__ mask,
                                                        float* __restrict__ out,
                                                        int count_idx) {
    const int cta = blockIdx.x;          // n*BH + by
    const int n  = cta / BH;
    const int by = cta - n * BH;
    const int t  = threadIdx.x;          // 128 threads
    const int warp = t >> 5, lane = t & 31;

    __shared__ __align__(16) float cm[W];   // slow path only
    __shared__ unsigned sball[9];            // 8 ballot words + zero pad
    __shared__ int s_last;
    __shared__ unsigned s_tot;

    // ---- 1) speculative output triples (no data dependency) ----
    {
        int j = t;                            // 219 floats: t and t+128
#pragma unroll
        for (int rep = 0; rep < 2; rep++, j += 128) {
            if (j < 3 * BW) {
                int c = j - (j / 3) * 3;
                int p = j / 3;
                float val = (c == 0) ? (float)n : (c == 1) ? (float)by : (float)p;
                out[(size_t)cta * (3 * BW) + j] = val;
            }
        }
    }

    const float4* base4 = (const float4*)(mask + (size_t)n * H * W);
    const float4* rowp  = base4 + (size_t)(by * BS) * (W / 4);

    // ---- 2) probe: two independent float4 loads per thread (same page) ----
    float4 va = rowp[t];
    float4 vb = rowp[t + 128];
    int hota = (va.x > 0.5f) | (va.y > 0.5f) | (va.z > 0.5f) | (va.w > 0.5f);
    int hotb = (vb.x > 0.5f) | (vb.y > 0.5f) | (vb.z > 0.5f) | (vb.w > 0.5f);
    unsigned bala = __ballot_sync(0xffffffffu, hota);   // chunks t      -> word warp
    unsigned balb = __ballot_sync(0xffffffffu, hotb);   // chunks t+128  -> word warp+4
    if (lane == 0) { sball[warp] = bala; sball[warp + 4] = balb; }
    if (t == 0) sball[8] = 0u;
    __syncthreads();

    int flag = 0;
    if (t < BW) {
        int lo = t * BS - 1; if (lo < 0) lo = 0;
        int hi = t * BS + 14;            // <= 1022, always in range
        int jlo = (lo + 3) >> 2;         // first fully-contained 4-chunk
        int jhi = (hi - 3) >> 2;         // last fully-contained 4-chunk
        int jw = jlo >> 5, jb = jlo & 31;
        unsigned long long w =
            ((unsigned long long)sball[jw + 1] << 32) | (unsigned long long)sball[jw];
        unsigned m = (1u << (jhi - jlo + 1)) - 1u;
        flag = ((w >> jb) & (unsigned long long)m) != 0ull;
    }
    int und = __syncthreads_count(t < BW && !flag);

    int csum;
    if (und == 0) {
        csum = BW;                        // fast path: every window active
    } else {
        // ---- 3) slow path (rare): thread t = chunks t, t+128 over 16 rows ----
        const int row0 = by * BS - 1;     // may be -1 (zero pad); row0+15 <= 1022
        {
            float4 m4a = make_float4(0.f, 0.f, 0.f, 0.f);
            float4 m4b = make_float4(0.f, 0.f, 0.f, 0.f);
#pragma unroll 4
            for (int r = 0; r < 16; r++) {
                int real = row0 + r;
                if (real >= 0) {
                    const float4* rp = base4 + (size_t)real * (W / 4);
                    float4 ua = rp[t];
                    float4 ub = rp[t + 128];
                    m4a.x = fmaxf(m4a.x, ua.x); m4a.y = fmaxf(m4a.y, ua.y);
                    m4a.z = fmaxf(m4a.z, ua.z); m4a.w = fmaxf(m4a.w, ua.w);
                    m4b.x = fmaxf(m4b.x, ub.x); m4b.y = fmaxf(m4b.y, ub.y);
                    m4b.z = fmaxf(m4b.z, ub.z); m4b.w = fmaxf(m4b.w, ub.w);
                }
            }
            ((float4*)cm)[t]       = m4a;
            ((float4*)cm)[t + 128] = m4b;
        }
        __syncthreads();

        int fl = 0;
        if (t < BW) {
            float mx = 0.f;
            int c0 = t * BS - 1;
#pragma unroll
            for (int k = 0; k < 16; k++) {
                int c = c0 + k;
                if (c >= 0) mx = fmaxf(mx, cm[c]);   // c <= 1022 guaranteed
            }
            fl = (mx > 0.5f) ? 1 : 0;
        }
        unsigned wb = __ballot_sync(0xffffffffu, fl);  // t<73 guard zeroes rest
        if (lane == 0 && warp < 3) g_bits[cta * 3 + warp] = wb;
        csum = __syncthreads_count(fl);
    }

    // ---- 4) release atomic: accumulate (count, done) ----
    if (t == 0) {
        g_csum[cta] = csum;
        unsigned long long add = (unsigned long long)(unsigned)csum | (1ull << 32);
        unsigned long long old;
        asm volatile("atom.add.release.gpu.u64 %0, [%1], %2;"
                     : "=l"(old) : "l"(&g_acc), "l"(add) : "memory");
        if ((unsigned)(old >> 32) == NROWS - 1) {
            s_last = 1;
            s_tot  = (unsigned)(old & 0xffffffffu) + (unsigned)csum;
        } else {
            s_last = 0;
        }
    }
    __syncthreads();
    if (!s_last) return;

    // last CTA: count slot, rare fixup, reset for next graph replay
    if (t == 0 && count_idx >= 0) out[count_idx] = (float)s_tot;
    if (s_tot != TOTAL) {
        asm volatile("fence.acquire.gpu;" ::: "memory");
        fixup(out, (int)s_tot);
    }
    __syncthreads();
    if (t == 0) g_acc = 0ull;
}

extern "C" void kernel_launch(void* const* d_in, const int* in_sizes, int n_in,
                              void* d_out, int out_size) {
    const float* mask = (const float*)d_in[0];
    float* out = (float*)d_out;

    int count_idx = (out_size > 3 * TOTAL) ? (out_size - 1) : -1;

    fused_kernel<<<NROWS, 128>>>(mask, out, count_idx);
}